// round 1
// baseline (speedup 1.0000x reference)
#include <cuda_runtime.h>
#include <cuda_bf16.h>

// Problem constants
#define B_   32
#define L_   1024
#define K_   64
#define N_   8
#define BLK_ (B_*L_*K_)          // 2,097,152 samples
#define CHUNK_L 32               // l-chunk per block in kernel A
#define CHUNKS  (L_/CHUNK_L)     // 32 chunks per b

// Output layout (flat f32, reference tuple order)
#define OFF_VQ  0L
#define OFF_HQ  4194304L
#define OFF_EBD 37748736L
#define OFF_EBC 39845888L
#define OFF_WD  41943040L
#define OFF_WC  48234496L

// Scratch (device globals: allocation-free)
__device__ float g_hp[BLK_];                  // h_power[b,l,k]  (8 MB)
__device__ float g_part[B_*CHUNKS*K_];        // per-(b,chunk,k) partial sums
__device__ float g_avg[B_*K_];                // avg_power[b,k]

// ---------------------------------------------------------------------------
// Kernel A: h_power + deterministic partial sums over l-chunks
// grid = B_*CHUNKS = 1024 blocks, 256 threads (4 l-lanes x 64 k-lanes)
// ---------------------------------------------------------------------------
__global__ __launch_bounds__(256) void kA_hpower(const float* __restrict__ H) {
    const int bx    = blockIdx.x;
    const int b     = bx >> 5;          // /CHUNKS
    const int chunk = bx & 31;
    const int tid   = threadIdx.x;
    const int k     = tid & 63;
    const int lsub  = tid >> 6;         // 0..3

    const float2* __restrict__ H2 = (const float2*)H;

    float partial = 0.0f;
#pragma unroll
    for (int r = 0; r < CHUNK_L/4; ++r) {
        const int l  = chunk*CHUNK_L + r*4 + lsub;
        const long bl = (long)b*L_ + l;
        float hp = 0.0f;
#pragma unroll
        for (int n = 0; n < N_; ++n) {
            float2 hv = H2[(bl*N_ + n)*K_ + k];
            hp = fmaf(hv.x, hv.x, fmaf(hv.y, hv.y, hp));
        }
        g_hp[bl*K_ + k] = hp;
        partial += hp;
    }

    __shared__ float sm[256];
    sm[tid] = partial;
    __syncthreads();
    if (tid < 64) {
        // fixed-order tree: deterministic
        float s = (sm[tid] + sm[tid+64]) + (sm[tid+128] + sm[tid+192]);
        g_part[bx*64 + tid] = s;
    }
}

// ---------------------------------------------------------------------------
// Kernel B: finalize avg_power[b,k] = (sum of 32 chunk partials) / 1024
// ---------------------------------------------------------------------------
__global__ void kB_avg() {
    int i = blockIdx.x*blockDim.x + threadIdx.x;
    if (i >= B_*K_) return;
    int b = i >> 6;
    int k = i & 63;
    float s = 0.0f;
#pragma unroll
    for (int c = 0; c < CHUNKS; ++c)
        s += g_part[(b*CHUNKS + c)*64 + k];
    g_avg[i] = s * (1.0f/1024.0f);
}

// ---------------------------------------------------------------------------
// lsq forward value: rintf(clip(x/s, Qn, Qp)) * s   (exact per Sterbenz)
// ---------------------------------------------------------------------------
__device__ __forceinline__ float lsqv(float x, float s, float Qn, float Qp) {
    float xc = fminf(fmaxf(x / s, Qn), Qp);
    return rintf(xc) * s;
}

// ---------------------------------------------------------------------------
// Kernel C: fused MLP + dual argmax + quantize + all outputs
// One thread per (b,l,k). grid = 8192 x 256.
// ---------------------------------------------------------------------------
__global__ __launch_bounds__(256) void kC_main(
    const float* __restrict__ v,   const float* __restrict__ H,
    const float* __restrict__ snr, const float* __restrict__ gd,
    const float* __restrict__ gc,
    const float* __restrict__ W1,  const float* __restrict__ b1,
    const float* __restrict__ W2,  const float* __restrict__ b2,
    const float* __restrict__ Wd,  const float* __restrict__ bd,
    const float* __restrict__ Wc,  const float* __restrict__ bc,
    const float* __restrict__ p_s2d, const float* __restrict__ p_s4d,
    const float* __restrict__ p_s2c, const float* __restrict__ p_s4c,
    float* __restrict__ out)
{
    __shared__ float sW1[5*32];
    __shared__ float sb1[32];
    __shared__ float sW2[32*32];
    __shared__ float sb2[32];
    __shared__ float sWd[32*3];
    __shared__ float sWc[32*3];
    __shared__ float sbd[3];
    __shared__ float sbc[3];

    const int tid = threadIdx.x;
    for (int i = tid; i < 5*32;  i += 256) sW1[i] = W1[i];
    for (int i = tid; i < 32*32; i += 256) sW2[i] = W2[i];
    for (int i = tid; i < 32*3;  i += 256) { sWd[i] = Wd[i]; sWc[i] = Wc[i]; }
    if (tid < 32) { sb1[tid] = b1[tid]; sb2[tid] = b2[tid]; }
    if (tid < 3)  { sbd[tid] = bd[tid]; sbc[tid] = bc[tid]; }
    __syncthreads();

    const int  gt = blockIdx.x*256 + tid;        // sample index, 0..BLK_-1
    const int  k  = gt & 63;
    const long bl = gt >> 6;                     // b*L + l
    const int  b  = gt >> 16;

    // ---- gather per-sample inputs ----
    const float2 vv   = ((const float2*)v)[gt];
    const float  snrv = snr[gt];
    const float  hpv  = g_hp[gt];
    const float  avgv = g_avg[(b<<6) | k];

    float pin[5] = { vv.x, vv.y, snrv, hpv, avgv };

    // ---- layer 1: 5 -> 32, relu ----
    float h1[32];
    {
        const float4* b1v = (const float4*)sb1;
        float acc[32];
#pragma unroll
        for (int j4 = 0; j4 < 8; ++j4) {
            float4 bb = b1v[j4];
            acc[j4*4+0] = bb.x; acc[j4*4+1] = bb.y;
            acc[j4*4+2] = bb.z; acc[j4*4+3] = bb.w;
        }
        const float4* W1v = (const float4*)sW1;
#pragma unroll
        for (int i = 0; i < 5; ++i) {
            float xv = pin[i];
#pragma unroll
            for (int j4 = 0; j4 < 8; ++j4) {
                float4 w = W1v[i*8 + j4];
                acc[j4*4+0] = fmaf(xv, w.x, acc[j4*4+0]);
                acc[j4*4+1] = fmaf(xv, w.y, acc[j4*4+1]);
                acc[j4*4+2] = fmaf(xv, w.z, acc[j4*4+2]);
                acc[j4*4+3] = fmaf(xv, w.w, acc[j4*4+3]);
            }
        }
#pragma unroll
        for (int j = 0; j < 32; ++j) h1[j] = fmaxf(acc[j], 0.0f);
    }

    // ---- layer 2: 32 -> 32, relu ----
    float h2[32];
    {
        const float4* b2v = (const float4*)sb2;
        float acc[32];
#pragma unroll
        for (int j4 = 0; j4 < 8; ++j4) {
            float4 bb = b2v[j4];
            acc[j4*4+0] = bb.x; acc[j4*4+1] = bb.y;
            acc[j4*4+2] = bb.z; acc[j4*4+3] = bb.w;
        }
        const float4* W2v = (const float4*)sW2;
#pragma unroll
        for (int i = 0; i < 32; ++i) {
            float xv = h1[i];
#pragma unroll
            for (int j4 = 0; j4 < 8; ++j4) {
                float4 w = W2v[i*8 + j4];
                acc[j4*4+0] = fmaf(xv, w.x, acc[j4*4+0]);
                acc[j4*4+1] = fmaf(xv, w.y, acc[j4*4+1]);
                acc[j4*4+2] = fmaf(xv, w.z, acc[j4*4+2]);
                acc[j4*4+3] = fmaf(xv, w.w, acc[j4*4+3]);
            }
        }
#pragma unroll
        for (int j = 0; j < 32; ++j) h2[j] = fmaxf(acc[j], 0.0f);
    }

    // ---- heads: 32 -> 3 (demod) and 32 -> 3 (channel) ----
    float ld0 = sbd[0], ld1 = sbd[1], ld2 = sbd[2];
    float lc0 = sbc[0], lc1 = sbc[1], lc2 = sbc[2];
#pragma unroll
    for (int i = 0; i < 32; ++i) {
        float xv = h2[i];
        ld0 = fmaf(xv, sWd[i*3+0], ld0);
        ld1 = fmaf(xv, sWd[i*3+1], ld1);
        ld2 = fmaf(xv, sWd[i*3+2], ld2);
        lc0 = fmaf(xv, sWc[i*3+0], lc0);
        lc1 = fmaf(xv, sWc[i*3+1], lc1);
        lc2 = fmaf(xv, sWc[i*3+2], lc2);
    }

    // ---- gumbel argmax (hard+y-sg(y) == one-hot exactly; softmax monotone) ----
    const long g3 = (long)gt * 3;
    float a0 = ld0 + gd[g3+0], a1 = ld1 + gd[g3+1], a2 = ld2 + gd[g3+2];
    int ad = 0; { float best = a0; if (a1 > best) { best = a1; ad = 1; } if (a2 > best) { ad = 2; } }
    float c0 = lc0 + gc[g3+0], c1 = lc1 + gc[g3+1], c2 = lc2 + gc[g3+2];
    int ac = 0; { float best = c0; if (c1 > best) { best = c1; ac = 1; } if (c2 > best) { ac = 2; } }

    const float S2d = __ldg(p_s2d), S4d = __ldg(p_s4d);
    const float S2c = __ldg(p_s2c), S4c = __ldg(p_s4c);

    const float wd1 = (ad == 1) ? 1.0f : 0.0f;
    const float wd2 = (ad == 2) ? 1.0f : 0.0f;
    const float wc1 = (ac == 1) ? 1.0f : 0.0f;
    const float wc2 = (ac == 2) ? 1.0f : 0.0f;

    // ---- v_q ----
    {
        float2 vq;
        vq.x = wd1 * lsqv(vv.x, S2d, -2.0f, 1.0f) + wd2 * lsqv(vv.x, S4d, -8.0f, 7.0f);
        vq.y = wd1 * lsqv(vv.y, S2d, -2.0f, 1.0f) + wd2 * lsqv(vv.y, S4d, -8.0f, 7.0f);
        ((float2*)(out + OFF_VQ))[gt] = vq;
    }

    // ---- expected bits ----
    out[OFF_EBD + gt] = wd1 * 4.0f  + wd2 * 8.0f;
    out[OFF_EBC + gt] = wc1 * 32.0f + wc2 * 64.0f;   // 2*N*2=32, 2*N*4=64 (N=8)

    // ---- one-hots ----
    out[OFF_WD + g3+0] = (ad == 0) ? 1.0f : 0.0f;
    out[OFF_WD + g3+1] = wd1;
    out[OFF_WD + g3+2] = wd2;
    out[OFF_WC + g3+0] = (ac == 0) ? 1.0f : 0.0f;
    out[OFF_WC + g3+1] = wc1;
    out[OFF_WC + g3+2] = wc2;

    // ---- H_q: 8 n's, coalesced float2 per n ----
    const float2* __restrict__ H2 = (const float2*)H;
    float2* __restrict__ HQ2 = (float2*)(out + OFF_HQ);
#pragma unroll
    for (int n = 0; n < N_; ++n) {
        const long hidx = (bl*N_ + n)*K_ + k;
        float2 hv = H2[hidx];
        float2 hq;
        hq.x = wc1 * lsqv(hv.x, S2c, -2.0f, 1.0f) + wc2 * lsqv(hv.x, S4c, -8.0f, 7.0f);
        hq.y = wc1 * lsqv(hv.y, S2c, -2.0f, 1.0f) + wc2 * lsqv(hv.y, S4c, -8.0f, 7.0f);
        HQ2[hidx] = hq;
    }
}

// ---------------------------------------------------------------------------
// Launch
// ---------------------------------------------------------------------------
extern "C" void kernel_launch(void* const* d_in, const int* in_sizes, int n_in,
                              void* d_out, int out_size) {
    const float* v   = (const float*)d_in[0];
    const float* H   = (const float*)d_in[1];
    const float* snr = (const float*)d_in[2];
    const float* gd  = (const float*)d_in[3];
    const float* gc  = (const float*)d_in[4];
    const float* W1  = (const float*)d_in[5];
    const float* b1  = (const float*)d_in[6];
    const float* W2  = (const float*)d_in[7];
    const float* b2  = (const float*)d_in[8];
    const float* Wd  = (const float*)d_in[9];
    const float* bd  = (const float*)d_in[10];
    const float* Wc  = (const float*)d_in[11];
    const float* bc  = (const float*)d_in[12];
    const float* s2d = (const float*)d_in[13];
    const float* s4d = (const float*)d_in[14];
    const float* s2c = (const float*)d_in[15];
    const float* s4c = (const float*)d_in[16];
    float* out = (float*)d_out;

    kA_hpower<<<B_*CHUNKS, 256>>>(H);
    kB_avg<<<(B_*K_ + 255)/256, 256>>>();
    kC_main<<<BLK_/256, 256>>>(v, H, snr, gd, gc,
                               W1, b1, W2, b2, Wd, bd, Wc, bc,
                               s2d, s4d, s2c, s4c, out);
}

// round 2
// speedup vs baseline: 1.4356x; 1.4356x over previous
#include <cuda_runtime.h>

// Problem constants
#define B_   32
#define L_   1024
#define K_   64
#define N_   8
#define BLK_ (B_*L_*K_)          // 2,097,152 samples
#define CHUNK_L 32
#define CHUNKS  (L_/CHUNK_L)

// Output layout (flat f32, reference tuple order)
#define OFF_VQ  0L
#define OFF_HQ  4194304L
#define OFF_EBD 37748736L
#define OFF_EBC 39845888L
#define OFF_WD  41943040L
#define OFF_WC  48234496L

#define RND_MAGIC 12582912.0f    // 1.5 * 2^23 : exact RNE round for |x| <= 8

typedef unsigned long long ull;

// Scratch (device globals: allocation-free)
__device__ float g_hp[BLK_];
__device__ float g_part[B_*CHUNKS*K_];
__device__ float g_avg[B_*K_];

// ---- packed f32x2 helpers (bitwise-exact dual fp32 ops) ----
__device__ __forceinline__ ull pack2(float x, float y) {
    ull r; asm("mov.b64 %0,{%1,%2};" : "=l"(r) : "f"(x), "f"(y)); return r;
}
__device__ __forceinline__ void unpack2(ull v, float& x, float& y) {
    asm("mov.b64 {%0,%1},%2;" : "=f"(x), "=f"(y) : "l"(v));
}
__device__ __forceinline__ ull ffma2(ull a, ull b, ull c) {
    ull d; asm("fma.rn.f32x2 %0,%1,%2,%3;" : "=l"(d) : "l"(a), "l"(b), "l"(c)); return d;
}

// ---------------------------------------------------------------------------
// Kernel A: h_power + deterministic partial sums over l-chunks
// ---------------------------------------------------------------------------
__global__ __launch_bounds__(256) void kA_hpower(const float* __restrict__ H) {
    const int bx    = blockIdx.x;
    const int b     = bx >> 5;
    const int chunk = bx & 31;
    const int tid   = threadIdx.x;
    const int k     = tid & 63;
    const int lsub  = tid >> 6;

    const float2* __restrict__ H2 = (const float2*)H;

    float partial = 0.0f;
#pragma unroll
    for (int r = 0; r < CHUNK_L/4; ++r) {
        const int l  = chunk*CHUNK_L + r*4 + lsub;
        const long bl = (long)b*L_ + l;
        float hp = 0.0f;
#pragma unroll
        for (int n = 0; n < N_; ++n) {
            float2 hv = H2[(bl*N_ + n)*K_ + k];
            hp = fmaf(hv.x, hv.x, fmaf(hv.y, hv.y, hp));
        }
        g_hp[bl*K_ + k] = hp;
        partial += hp;
    }

    __shared__ float sm[256];
    sm[tid] = partial;
    __syncthreads();
    if (tid < 64) {
        float s = (sm[tid] + sm[tid+64]) + (sm[tid+128] + sm[tid+192]);
        g_part[bx*64 + tid] = s;
    }
}

// ---------------------------------------------------------------------------
// Kernel B: finalize avg_power
// ---------------------------------------------------------------------------
__global__ void kB_avg() {
    int i = blockIdx.x*blockDim.x + threadIdx.x;
    if (i >= B_*K_) return;
    int b = i >> 6;
    int k = i & 63;
    float s = 0.0f;
#pragma unroll
    for (int c = 0; c < CHUNKS; ++c)
        s += g_part[(b*CHUNKS + c)*64 + k];
    g_avg[i] = s * (1.0f/1024.0f);
}

// ---------------------------------------------------------------------------
// lsq forward: round(clip(x*rs, Qn, Qp)) * s, exact RNE via magic constant.
// ---------------------------------------------------------------------------
__device__ __forceinline__ float lsqv(float x, float rs, float s, float qn, float qp) {
    float t = x * rs;
    t = fminf(fmaxf(t, qn), qp);
    t = __fadd_rn(__fadd_rn(t, RND_MAGIC), -RND_MAGIC);
    return t * s;
}

// ---------------------------------------------------------------------------
// Kernel C: fused MLP (f32x2) + dual argmax + quantize + all outputs
// ---------------------------------------------------------------------------
__global__ __launch_bounds__(256) void kC_main(
    const float* __restrict__ v,   const float* __restrict__ H,
    const float* __restrict__ snr, const float* __restrict__ gd,
    const float* __restrict__ gc,
    const float* __restrict__ W1,  const float* __restrict__ b1,
    const float* __restrict__ W2,  const float* __restrict__ b2,
    const float* __restrict__ Wd,  const float* __restrict__ bd,
    const float* __restrict__ Wc,  const float* __restrict__ bc,
    const float* __restrict__ p_s2d, const float* __restrict__ p_s4d,
    const float* __restrict__ p_s2c, const float* __restrict__ p_s4c,
    float* __restrict__ out)
{
    __shared__ __align__(16) ull   sW1[5*16];    // W1 pairs along output dim
    __shared__ __align__(16) ull   sW2[32*16];   // W2 pairs along output dim
    __shared__ __align__(16) float sWh[32*8];    // per i: d0 d1 d2 c0 c1 c2 0 0
    __shared__ __align__(16) float sb1[32];
    __shared__ __align__(16) float sb2[32];
    __shared__ float sbh[6];
    __shared__ float sS[8];                      // S2d S4d S2c S4c  R2d R4d R2c R4c

    const int tid = threadIdx.x;
    {
        float* w1f = (float*)sW1;
        for (int i = tid; i < 160;  i += 256) w1f[i] = W1[i];
        float* w2f = (float*)sW2;
        for (int i = tid; i < 1024; i += 256) w2f[i] = W2[i];
        if (tid < 32) {
            sb1[tid] = b1[tid];
            sb2[tid] = b2[tid];
            sWh[tid*8+0] = Wd[tid*3+0];
            sWh[tid*8+1] = Wd[tid*3+1];
            sWh[tid*8+2] = Wd[tid*3+2];
            sWh[tid*8+3] = Wc[tid*3+0];
            sWh[tid*8+4] = Wc[tid*3+1];
            sWh[tid*8+5] = Wc[tid*3+2];
            sWh[tid*8+6] = 0.0f;
            sWh[tid*8+7] = 0.0f;
        }
        if (tid < 6) sbh[tid] = (tid < 3) ? bd[tid] : bc[tid-3];
        if (tid == 0) {
            float a = *p_s2d, bq = *p_s4d, c = *p_s2c, d = *p_s4c;
            sS[0] = a;  sS[1] = bq;  sS[2] = c;  sS[3] = d;
            sS[4] = 1.0f/a; sS[5] = 1.0f/bq; sS[6] = 1.0f/c; sS[7] = 1.0f/d;
        }
    }
    __syncthreads();

    const int  gt = blockIdx.x*256 + tid;
    const int  k  = gt & 63;
    const long bl = gt >> 6;
    const int  b  = gt >> 16;

    const float2 vv   = ((const float2*)v)[gt];
    const float  snrv = snr[gt];
    const float  hpv  = g_hp[gt];
    const float  avgv = g_avg[(b<<6) | k];

    float pin[5] = { vv.x, vv.y, snrv, hpv, avgv };

    // ---- layer 1: 5 -> 32 (f32x2), relu ----
    ull acc[16];
    {
        const ull* bp = (const ull*)sb1;
#pragma unroll
        for (int j = 0; j < 16; ++j) acc[j] = bp[j];
#pragma unroll
        for (int i = 0; i < 5; ++i) {
            ull xx = pack2(pin[i], pin[i]);
            const ulonglong2* wr = (const ulonglong2*)(sW1 + i*16);
#pragma unroll
            for (int j2 = 0; j2 < 8; ++j2) {
                ulonglong2 w = wr[j2];
                acc[j2*2+0] = ffma2(xx, w.x, acc[j2*2+0]);
                acc[j2*2+1] = ffma2(xx, w.y, acc[j2*2+1]);
            }
        }
    }
    float h1[32];
#pragma unroll
    for (int j = 0; j < 16; ++j) {
        float a, bq; unpack2(acc[j], a, bq);
        h1[2*j]   = fmaxf(a, 0.0f);
        h1[2*j+1] = fmaxf(bq, 0.0f);
    }

    // ---- layer 2: 32 -> 32 (f32x2), relu ----
    {
        const ull* bp = (const ull*)sb2;
#pragma unroll
        for (int j = 0; j < 16; ++j) acc[j] = bp[j];
#pragma unroll
        for (int i = 0; i < 32; ++i) {
            ull xx = pack2(h1[i], h1[i]);
            const ulonglong2* wr = (const ulonglong2*)(sW2 + i*16);
#pragma unroll
            for (int j2 = 0; j2 < 8; ++j2) {
                ulonglong2 w = wr[j2];
                acc[j2*2+0] = ffma2(xx, w.x, acc[j2*2+0]);
                acc[j2*2+1] = ffma2(xx, w.y, acc[j2*2+1]);
            }
        }
    }
    float h2[32];
#pragma unroll
    for (int j = 0; j < 16; ++j) {
        float a, bq; unpack2(acc[j], a, bq);
        h2[2*j]   = fmaxf(a, 0.0f);
        h2[2*j+1] = fmaxf(bq, 0.0f);
    }

    // ---- heads: 32 -> 3 + 3 packed as (d0,d1)(d2,c0)(c1,c2) ----
    ull p0 = pack2(sbh[0], sbh[1]);
    ull p1 = pack2(sbh[2], sbh[3]);
    ull p2 = pack2(sbh[4], sbh[5]);
    {
        const ulonglong2* whv = (const ulonglong2*)sWh;
        const ull*        whu = (const ull*)sWh;
#pragma unroll
        for (int i = 0; i < 32; ++i) {
            ull xx = pack2(h2[i], h2[i]);
            ulonglong2 wa = whv[i*2];
            ull wb = whu[i*4+2];
            p0 = ffma2(xx, wa.x, p0);
            p1 = ffma2(xx, wa.y, p1);
            p2 = ffma2(xx, wb,   p2);
        }
    }
    float ld0, ld1, ld2, lc0, lc1, lc2;
    unpack2(p0, ld0, ld1);
    unpack2(p1, ld2, lc0);
    unpack2(p2, lc1, lc2);

    // ---- gumbel argmax (one-hot exact: hard + y - sg(y) == hard) ----
    const long g3 = (long)gt * 3;
    float a0 = ld0 + gd[g3+0], a1 = ld1 + gd[g3+1], a2 = ld2 + gd[g3+2];
    int ad = 0; { float best = a0; if (a1 > best) { best = a1; ad = 1; } if (a2 > best) { ad = 2; } }
    float c0 = lc0 + gc[g3+0], c1 = lc1 + gc[g3+1], c2 = lc2 + gc[g3+2];
    int ac = 0; { float best = c0; if (c1 > best) { best = c1; ac = 1; } if (c2 > best) { ac = 2; } }

    // ---- per-sample quantizer selection (one branch, exact vs one-hot sum) ----
    const bool  fd  = (ad != 0);
    const float sd  = (ad == 2) ? sS[1] : sS[0];
    const float rsd = (ad == 2) ? sS[5] : sS[4];
    const float qnd = (ad == 2) ? -8.0f : -2.0f;
    const float qpd = (ad == 2) ?  7.0f :  1.0f;

    const bool  fc  = (ac != 0);
    const float sc  = (ac == 2) ? sS[3] : sS[2];
    const float rsc = (ac == 2) ? sS[7] : sS[6];
    const float qnc = (ac == 2) ? -8.0f : -2.0f;
    const float qpc = (ac == 2) ?  7.0f :  1.0f;

    // ---- v_q ----
    {
        float2 vq;
        vq.x = fd ? lsqv(vv.x, rsd, sd, qnd, qpd) : 0.0f;
        vq.y = fd ? lsqv(vv.y, rsd, sd, qnd, qpd) : 0.0f;
        ((float2*)(out + OFF_VQ))[gt] = vq;
    }

    // ---- expected bits ----
    out[OFF_EBD + gt] = (ad == 1) ? 4.0f  : ((ad == 2) ? 8.0f  : 0.0f);
    out[OFF_EBC + gt] = (ac == 1) ? 32.0f : ((ac == 2) ? 64.0f : 0.0f);

    // ---- one-hots ----
    out[OFF_WD + g3+0] = (ad == 0) ? 1.0f : 0.0f;
    out[OFF_WD + g3+1] = (ad == 1) ? 1.0f : 0.0f;
    out[OFF_WD + g3+2] = (ad == 2) ? 1.0f : 0.0f;
    out[OFF_WC + g3+0] = (ac == 0) ? 1.0f : 0.0f;
    out[OFF_WC + g3+1] = (ac == 1) ? 1.0f : 0.0f;
    out[OFF_WC + g3+2] = (ac == 2) ? 1.0f : 0.0f;

    // ---- H_q ----
    const float2* __restrict__ H2 = (const float2*)H;
    float2* __restrict__ HQ2 = (float2*)(out + OFF_HQ);
#pragma unroll
    for (int n = 0; n < N_; ++n) {
        const long hidx = (bl*N_ + n)*K_ + k;
        float2 hv = H2[hidx];
        float2 hq;
        hq.x = fc ? lsqv(hv.x, rsc, sc, qnc, qpc) : 0.0f;
        hq.y = fc ? lsqv(hv.y, rsc, sc, qnc, qpc) : 0.0f;
        HQ2[hidx] = hq;
    }
}

// ---------------------------------------------------------------------------
// Launch
// ---------------------------------------------------------------------------
extern "C" void kernel_launch(void* const* d_in, const int* in_sizes, int n_in,
                              void* d_out, int out_size) {
    const float* v   = (const float*)d_in[0];
    const float* H   = (const float*)d_in[1];
    const float* snr = (const float*)d_in[2];
    const float* gd  = (const float*)d_in[3];
    const float* gc  = (const float*)d_in[4];
    const float* W1  = (const float*)d_in[5];
    const float* b1  = (const float*)d_in[6];
    const float* W2  = (const float*)d_in[7];
    const float* b2  = (const float*)d_in[8];
    const float* Wd  = (const float*)d_in[9];
    const float* bd  = (const float*)d_in[10];
    const float* Wc  = (const float*)d_in[11];
    const float* bc  = (const float*)d_in[12];
    const float* s2d = (const float*)d_in[13];
    const float* s4d = (const float*)d_in[14];
    const float* s2c = (const float*)d_in[15];
    const float* s4c = (const float*)d_in[16];
    float* out = (float*)d_out;

    kA_hpower<<<B_*CHUNKS, 256>>>(H);
    kB_avg<<<(B_*K_ + 255)/256, 256>>>();
    kC_main<<<BLK_/256, 256>>>(v, H, snr, gd, gc,
                               W1, b1, W2, b2, Wd, bd, Wc, bc,
                               s2d, s4d, s2c, s4c, out);
}